// round 3
// baseline (speedup 1.0000x reference)
#include <cuda_runtime.h>
#include <cuda_bf16.h>

#define LUT_N 32768

// LUT over logit in [-16, 16]: g_lut[i] = (F(x_i), F(x_{i+1})) for one-load lerp.
static __device__ float2 g_lut[LUT_N];

__global__ void build_lut_kernel(const float* __restrict__ basis,
                                 const float* __restrict__ w1,
                                 const float* __restrict__ b1,
                                 const float* __restrict__ w2,
                                 const float* __restrict__ b2) {
    int i = blockIdx.x * blockDim.x + threadIdx.x;
    if (i >= LUT_N) return;
    const float step = 32.0f / (float)(LUT_N - 1);
    float x = fmaf((float)i, step, -16.0f);

    // act = sigmoid(x)
    float act = 1.0f / (1.0f + expf(-x));

    // RBF features vs 8 basis rows (each 4-dim)
    float feats[8];
#pragma unroll
    for (int b = 0; b < 8; ++b) {
        float s = 0.0f;
#pragma unroll
        for (int j = 0; j < 4; ++j) {
            float d = act - basis[b * 4 + j];
            s = fmaf(d, d, s);
        }
        feats[b] = expf(-s);   // GAMMA = 1
    }

    // MLP: Linear(8,16) -> tanh -> Linear(16,1)
    float out = b2[0];
#pragma unroll
    for (int j = 0; j < 16; ++j) {
        float hj = b1[j];
#pragma unroll
        for (int b = 0; b < 8; ++b)
            hj = fmaf(feats[b], w1[b * 16 + j], hj);
        out = fmaf(tanhf(hj), w2[j], out);
    }

    g_lut[i].x = out;
    if (i > 0) g_lut[i - 1].y = out;   // disjoint 4B words, no race
}

__global__ __launch_bounds__(256) void eval_kernel(
    const float4* __restrict__ data,   // [N] patches, each one float4
    const float* __restrict__ conv_w,  // 4 floats
    const float* __restrict__ conv_b,  // 1 float
    float* __restrict__ out,           // [N]
    int n) {
    const float cw0 = __ldg(conv_w + 0);
    const float cw1 = __ldg(conv_w + 1);
    const float cw2 = __ldg(conv_w + 2);
    const float cw3 = __ldg(conv_w + 3);
    const float cb  = __ldg(conv_b);
    const float inv_step = (float)(LUT_N - 1) / 32.0f;

    int base = blockIdx.x * (256 * 4) + threadIdx.x;

    if (base + 3 * 256 < n) {
        // Fast path: 4 front-batched coalesced LDG.128
        float4 d0 = data[base];
        float4 d1 = data[base + 256];
        float4 d2 = data[base + 512];
        float4 d3 = data[base + 768];

        float r[4];
        float4 dd[4] = {d0, d1, d2, d3};
#pragma unroll
        for (int k = 0; k < 4; ++k) {
            float4 d = dd[k];
            float logit = fmaf(d.x, cw0, fmaf(d.y, cw1, fmaf(d.z, cw2, fmaf(d.w, cw3, cb))));
            float u = (logit + 16.0f) * inv_step;
            u = fminf(fmaxf(u, 0.0f), (float)(LUT_N - 1));
            int i = min((int)u, LUT_N - 2);
            float frac = u - (float)i;
            float2 p = g_lut[i];
            r[k] = fmaf(frac, p.y - p.x, p.x);
        }
#pragma unroll
        for (int k = 0; k < 4; ++k)
            out[base + k * 256] = r[k];
    } else {
        // Tail path (never taken for N = 8388608, kept for generality)
        for (int k = 0; k < 4; ++k) {
            int idx = base + k * 256;
            if (idx < n) {
                float4 d = data[idx];
                float logit = fmaf(d.x, cw0, fmaf(d.y, cw1, fmaf(d.z, cw2, fmaf(d.w, cw3, cb))));
                float u = (logit + 16.0f) * inv_step;
                u = fminf(fmaxf(u, 0.0f), (float)(LUT_N - 1));
                int i = min((int)u, LUT_N - 2);
                float frac = u - (float)i;
                float2 p = g_lut[i];
                out[idx] = fmaf(frac, p.y - p.x, p.x);
            }
        }
    }
}

extern "C" void kernel_launch(void* const* d_in, const int* in_sizes, int n_in,
                              void* d_out, int out_size) {
    const float* data   = (const float*)d_in[0];  // [N, 2, 2]
    // d_in[1] = conv_w, d_in[2] = conv_b
    const float* basis  = (const float*)d_in[3];  // [8, 4]
    const float* w1     = (const float*)d_in[4];  // [8, 16]
    const float* b1     = (const float*)d_in[5];  // [16]
    const float* w2     = (const float*)d_in[6];  // [16, 1]
    const float* b2     = (const float*)d_in[7];  // [1]

    int n = out_size;  // N patches, one output each

    build_lut_kernel<<<(LUT_N + 255) / 256, 256>>>(basis, w1, b1, w2, b2);

    int blocks = (n + 1023) / 1024;
    eval_kernel<<<blocks, 256>>>((const float4*)data,
                                 (const float*)d_in[1],
                                 (const float*)d_in[2],
                                 (float*)d_out, n);
}